// round 15
// baseline (speedup 1.0000x reference)
#include <cuda_runtime.h>
#include <cuda_bf16.h>
#include <cstdint>

#define P_CONST 524288

// ---- bias float indices in sf[] ----
#define SF_BB1  0
#define SF_BB2  64
#define SF_VB1  96
#define SF_VB2  128
#define SF_RB1  160
#define SF_RB2  192
#define SF_RB3  208        // 8 slots (3 real + 5 zero)

// ---- smem byte offsets (W1A/W1B live in GLOBAL g_w1) ----
#define BW2  1152u               // 16 tiles (4x4)
#define BV1  (BW2  + 16u*512u)   // 8 tiles  (4x2)
#define BV2  (BV1  +  8u*512u)   // 8 tiles
#define BR1  (BV2  +  8u*512u)   // 24 tiles (3 views x 4x2)
#define BR2  (BR1  + 24u*512u)   // 4 tiles  (2x2)
#define BR3  (BR2  +  4u*512u)   // 1 tile   (rw3 3x16 padded)
#define AWBASE (BR3 + 512u)      // per-warp A1 staging, 9216B each (4 warps)
#define SMEM_TC (AWBASE + 4u*9216u)   // 69248 B -> 3 CTAs/SM (12 warps)

__device__ float g_scr[(size_t)P_CONST * 105];   // input transposed [P/32][105][32]
__device__ uint4 g_w1[64 * 32];                  // fragment-packed W1A(40)+W1B(24) tiles

// ========================= helpers =========================
__device__ __forceinline__ float elu1(float x) {
    return x > 0.f ? x : (__expf(x) - 1.f);
}
__device__ __forceinline__ void bsplit(float x, __nv_bfloat16 &h, __nv_bfloat16 &l) {
    h = __float2bfloat16(x);
    l = __float2bfloat16(x - __bfloat162float(h));
}
__device__ __forceinline__ uint32_t bpack(__nv_bfloat16 a, __nv_bfloat16 b) {
    __nv_bfloat162 t(a, b);
    return *reinterpret_cast<uint32_t*>(&t);
}
__device__ __forceinline__ void pack_hl(float x, float y, uint32_t &hi, uint32_t &lo) {
    asm("cvt.rn.bf16x2.f32 %0, %1, %2;" : "=r"(hi) : "f"(y), "f"(x));
    uint32_t hxf = hi << 16;
    uint32_t hyf = hi & 0xFFFF0000u;
    float lx = x - __uint_as_float(hxf);
    float ly = y - __uint_as_float(hyf);
    asm("cvt.rn.bf16x2.f32 %0, %1, %2;" : "=r"(lo) : "f"(ly), "f"(lx));
}

// mma.m16n8k16 row.col f32 += bf16*bf16
__device__ __forceinline__ void mma_bf(float* d, const uint32_t* a, uint32_t b0, uint32_t b1) {
    asm volatile(
        "mma.sync.aligned.m16n8k16.row.col.f32.bf16.bf16.f32 "
        "{%0,%1,%2,%3}, {%4,%5,%6,%7}, {%8,%9}, {%0,%1,%2,%3};"
        : "+f"(d[0]), "+f"(d[1]), "+f"(d[2]), "+f"(d[3])
        : "r"(a[0]), "r"(a[1]), "r"(a[2]), "r"(a[3]), "r"(b0), "r"(b1));
}
// single-accumulator 3-term (head tail only)
__device__ __forceinline__ void mma3(float* d, const uint32_t* ah, const uint32_t* al, uint4 bt) {
    mma_bf(d, ah, bt.x, bt.y);
    mma_bf(d, al, bt.x, bt.y);
    mma_bf(d, ah, bt.z, bt.w);
}
// TERM-MAJOR multi-accumulator 3-term split: consecutive mmas hit different D
template<int N>
__device__ __forceinline__ void mma3_multi(float (*d)[4], const uint32_t* ah,
                                           const uint32_t* al, const uint4* bt) {
#pragma unroll
    for (int n = 0; n < N; ++n) mma_bf(d[n], ah, bt[n].x, bt[n].y);
#pragma unroll
    for (int n = 0; n < N; ++n) mma_bf(d[n], al, bt[n].x, bt[n].y);
#pragma unroll
    for (int n = 0; n < N; ++n) mma_bf(d[n], ah, bt[n].z, bt[n].w);
}
// A fragment from smem bf16 matrix [16 x cols], row stride rs bytes
__device__ __forceinline__ void load_afrag(uint32_t* a, const char* sb, uint32_t base,
                                           int rs, int col0, int g) {
    a[0] = *reinterpret_cast<const uint32_t*>(sb + base + g * rs + col0 * 2);
    a[1] = *reinterpret_cast<const uint32_t*>(sb + base + (g + 8) * rs + col0 * 2);
    a[2] = *reinterpret_cast<const uint32_t*>(sb + base + g * rs + (col0 + 8) * 2);
    a[3] = *reinterpret_cast<const uint32_t*>(sb + base + (g + 8) * rs + (col0 + 8) * 2);
}
__device__ __forceinline__ void dinit(float* d, const float* sf, int boff, int nt, int t) {
    float b0 = sf[boff + nt * 8 + t * 2];
    float b1 = sf[boff + nt * 8 + t * 2 + 1];
    d[0] = b0; d[1] = b1; d[2] = b0; d[3] = b1;
}
__device__ __forceinline__ void pack_frag_elu(const float* dA, const float* dB,
                                              uint32_t* ah, uint32_t* al) {
    pack_hl(elu1(dA[0]), elu1(dA[1]), ah[0], al[0]);
    pack_hl(elu1(dA[2]), elu1(dA[3]), ah[1], al[1]);
    pack_hl(elu1(dB[0]), elu1(dB[1]), ah[2], al[2]);
    pack_hl(elu1(dB[2]), elu1(dB[3]), ah[3], al[3]);
}
__device__ __forceinline__ void pack_frag_raw(const float* dA, const float* dB,
                                              uint32_t* ah, uint32_t* al) {
    pack_hl(dA[0], dA[1], ah[0], al[0]);
    pack_hl(dA[2], dA[3], ah[1], al[1]);
    pack_hl(dB[0], dB[1], ah[2], al[2]);
    pack_hl(dB[2], dB[3], ah[3], al[3]);
}

// stage weight matrix w[N][K] (row stride ldw floats) as fragment-packed B tiles (SMEM)
__device__ void stage_B(char* sb, uint32_t off, const float* __restrict__ w,
                        int N, int K, int ldw, float scale, int NT, int KT,
                        int wid, int lane) {
    int g = lane >> 2, t = lane & 3;
    for (int tile = wid; tile < NT * KT; tile += 4) {
        int kt = tile / NT, nt = tile % NT;
        int n = nt * 8 + g;
        int k0 = kt * 16 + t * 2;
        float v0 = 0.f, v1 = 0.f, v2 = 0.f, v3 = 0.f;
        if (n < N) {
            if (k0 < K)     v0 = __ldg(w + n * ldw + k0) * scale;
            if (k0 + 1 < K) v1 = __ldg(w + n * ldw + k0 + 1) * scale;
            if (k0 + 8 < K) v2 = __ldg(w + n * ldw + k0 + 8) * scale;
            if (k0 + 9 < K) v3 = __ldg(w + n * ldw + k0 + 9) * scale;
        }
        __nv_bfloat16 h0, l0, h1, l1, h2, l2, h3, l3;
        bsplit(v0, h0, l0); bsplit(v1, h1, l1);
        bsplit(v2, h2, l2); bsplit(v3, h3, l3);
        uint4 u;
        u.x = bpack(h0, h1);
        u.y = bpack(h2, h3);
        u.z = bpack(l0, l1);
        u.w = bpack(l2, l3);
        *reinterpret_cast<uint4*>(sb + off + ((uint32_t)tile * 32u + lane) * 16u) = u;
    }
}

// ============== K0a: pack W1A/W1B fragment tiles into global g_w1 ================
__global__ __launch_bounds__(256)
void k_wpack(const float* __restrict__ bw1)
{
    int gid = blockIdx.x * 256 + threadIdx.x;
    if (gid >= 64 * 32) return;
    int tile = gid >> 5, lane = gid & 31;
    int g = lane >> 2, t = lane & 3;
    const float* w;
    int kt, nt, K;
    if (tile < 40) { kt = tile / 8; nt = tile % 8; w = bw1;      K = 70; }
    else { int u2 = tile - 40; kt = u2 / 8; nt = u2 % 8; w = bw1 + 70; K = 35; }
    int n = nt * 8 + g;
    int k0 = kt * 16 + t * 2;
    float v0 = 0.f, v1 = 0.f, v2 = 0.f, v3 = 0.f;
    if (k0 < K)     v0 = __ldg(w + n * 105 + k0);
    if (k0 + 1 < K) v1 = __ldg(w + n * 105 + k0 + 1);
    if (k0 + 8 < K) v2 = __ldg(w + n * 105 + k0 + 8);
    if (k0 + 9 < K) v3 = __ldg(w + n * 105 + k0 + 9);
    __nv_bfloat16 h0, l0, h1, l1, h2, l2, h3, l3;
    bsplit(v0, h0, l0); bsplit(v1, h1, l1);
    bsplit(v2, h2, l2); bsplit(v3, h3, l3);
    uint4 u;
    u.x = bpack(h0, h1);
    u.y = bpack(h2, h3);
    u.z = bpack(l0, l1);
    u.w = bpack(l2, l3);
    g_w1[tile * 32 + lane] = u;
}

// ================= K0: transpose input to [P/32][105][32] + emit rgb_in ==========
__global__ __launch_bounds__(256, 4)
void k_prep(const float* __restrict__ rgb, float* __restrict__ out_in, int P)
{
    __shared__ float st[32 * 105];
    const int g = blockIdx.x;
    const int tid = threadIdx.x;

    const float4* src4 = reinterpret_cast<const float4*>(rgb + (size_t)g * 3360);
    float4* st4 = reinterpret_cast<float4*>(st);
#pragma unroll
    for (int i = tid; i < 840; i += 256) st4[i] = src4[i];
    __syncthreads();

    float* dst = g_scr + (size_t)g * 3360;
#pragma unroll
    for (int i = tid; i < 3360; i += 256) {
        int j = i >> 5, lane = i & 31;
        dst[i] = st[lane * 105 + j];
    }
    for (int i = tid; i < 288; i += 256) {
        int pl = i / 9, r = i % 9, v = r / 3, k = r % 3;
        out_in[((size_t)g * 32 + pl) * 9 + r] = st[pl * 105 + v * 35 + k];
    }
}

// ====== K1: HMMA term-major MLP, 128 thr, 3 CTAs/SM (12 warps) ===================
__global__ __launch_bounds__(128, 3)
void k_tc(
    const float* __restrict__ bw1, const float* __restrict__ bb1,
    const float* __restrict__ bw2, const float* __restrict__ bb2,
    const float* __restrict__ vw1, const float* __restrict__ vb1,
    const float* __restrict__ vw2, const float* __restrict__ vb2,
    const float* __restrict__ rw1, const float* __restrict__ rb1,
    const float* __restrict__ rw2, const float* __restrict__ rb2,
    const float* __restrict__ rw3, const float* __restrict__ rb3,
    float* __restrict__ out_rgb, int P)
{
    extern __shared__ char sb[];
    float* sf = reinterpret_cast<float*>(sb);
    const int tid = threadIdx.x;
    const int wid = tid >> 5;
    const int lane = tid & 31;
    const int g = lane >> 2;
    const int t = lane & 3;

    // ---- stage biases ----
    for (int i = tid; i < 64; i += 128) sf[SF_BB1 + i] = bb1[i];
    for (int i = tid; i < 32; i += 128) sf[SF_BB2 + i] = bb2[i];
    for (int i = tid; i < 32; i += 128) sf[SF_VB1 + i] = vb1[i];
    for (int i = tid; i < 32; i += 128) sf[SF_VB2 + i] = vb2[i];
    for (int i = tid; i < 32; i += 128) sf[SF_RB1 + i] = rb1[i];
    for (int i = tid; i < 16; i += 128) sf[SF_RB2 + i] = rb2[i];
    for (int i = tid; i < 8;  i += 128) sf[SF_RB3 + i] = (i < 3) ? rb3[i] : 0.f;

    // ---- stage small weights ----
    stage_B(sb, BW2,  bw2,      32, 64, 64,  1.f,       4, 4, wid, lane);
    stage_B(sb, BV1,  vw1,      32, 32, 32,  1.f / 3.f, 4, 2, wid, lane);
    stage_B(sb, BV2,  vw2,      32, 32, 32,  1.f,       4, 2, wid, lane);
    for (int v = 0; v < 3; ++v)
        stage_B(sb, BR1 + (uint32_t)v * 8u * 512u, rw1 + v * 32, 32, 32, 96, 1.f, 4, 2, wid, lane);
    stage_B(sb, BR2,  rw2,      16, 32, 32,  1.f,       2, 2, wid, lane);
    stage_B(sb, BR3,  rw3,      3, 16, 16,   1.f,       1, 1, wid, lane);

    // per-warp A1 staging bases
    const uint32_t aw   = AWBASE + (uint32_t)wid * 9216u;
    const uint32_t A1AH = aw, A1AL = aw + 2816u;
    const uint32_t A1BH = aw + 5632u, A1BL = aw + 7424u;

    // zero pads: A1a cols 70..79, A1b cols 35..47
    for (int i = lane; i < 160; i += 32) {
        int q = i / 10, c = 70 + i % 10;
        *reinterpret_cast<__nv_bfloat16*>(sb + A1AH + q * 176 + c * 2) = __float2bfloat16(0.f);
        *reinterpret_cast<__nv_bfloat16*>(sb + A1AL + q * 176 + c * 2) = __float2bfloat16(0.f);
    }
    for (int i = lane; i < 208; i += 32) {
        int q = i / 13, c = 35 + i % 13;
        *reinterpret_cast<__nv_bfloat16*>(sb + A1BH + q * 112 + c * 2) = __float2bfloat16(0.f);
        *reinterpret_cast<__nv_bfloat16*>(sb + A1BL + q * 112 + c * 2) = __float2bfloat16(0.f);
    }
    __syncthreads();

    const int ntile = P / 64;
    for (int tile = blockIdx.x; tile < ntile; tile += gridDim.x) {
        const float* gb = g_scr + (size_t)(tile * 2 + (wid >> 1)) * 3360 + (wid & 1) * 16;

        // ---- stats -> A1a ----
        for (int i = lane; i < 560; i += 32) {
            int q = i & 15, k = i >> 4;
            float a = __ldg(gb + k * 32 + q);
            float b = __ldg(gb + (35 + k) * 32 + q);
            float c = __ldg(gb + (70 + k) * 32 + q);
            float m = (a + b + c) * (1.f / 3.f);
            float qv = fmaf(-m, m, fmaf(a, a, fmaf(b, b, c * c)) * (1.f / 3.f));
            __nv_bfloat16 h, l;
            bsplit(m, h, l);
            *reinterpret_cast<__nv_bfloat16*>(sb + A1AH + q * 176 + k * 2) = h;
            *reinterpret_cast<__nv_bfloat16*>(sb + A1AL + q * 176 + k * 2) = l;
            bsplit(qv, h, l);
            *reinterpret_cast<__nv_bfloat16*>(sb + A1AH + q * 176 + (35 + k) * 2) = h;
            *reinterpret_cast<__nv_bfloat16*>(sb + A1AL + q * 176 + (35 + k) * 2) = l;
        }
        __syncwarp();

        // ---- g1 = bb1 + A1a @ W1a^T (term-major, bt[8] prefetched) ----
        float g1d[8][4];
#pragma unroll
        for (int nt = 0; nt < 8; ++nt) dinit(g1d[nt], sf, SF_BB1, nt, t);
#pragma unroll
        for (int kt = 0; kt < 5; ++kt) {
            uint32_t ah[4], al[4];
            load_afrag(ah, sb, A1AH, 176, kt * 16 + t * 2, g);
            load_afrag(al, sb, A1AL, 176, kt * 16 + t * 2, g);
            uint4 bt[8];
#pragma unroll
            for (int nt = 0; nt < 8; ++nt) bt[nt] = __ldg(&g_w1[(kt * 8 + nt) * 32 + lane]);
            mma3_multi<8>(g1d, ah, al, bt);
        }

        float r1d[4][4];
#pragma unroll
        for (int nt = 0; nt < 4; ++nt) dinit(r1d[nt], sf, SF_RB1, nt, t);

        // ---- per-view ----
#pragma unroll 1
        for (int v = 0; v < 3; ++v) {
            // A1b = f_v
            for (int i = lane; i < 560; i += 32) {
                int q = i & 15, k = i >> 4;
                float fv = __ldg(gb + (v * 35 + k) * 32 + q);
                __nv_bfloat16 h, l;
                bsplit(fv, h, l);
                *reinterpret_cast<__nv_bfloat16*>(sb + A1BH + q * 112 + k * 2) = h;
                *reinterpret_cast<__nv_bfloat16*>(sb + A1BL + q * 112 + k * 2) = l;
            }
            __syncwarp();

            // L1: d1 = g1 + A1b @ W1b^T (term-major)
            float d1[8][4];
#pragma unroll
            for (int nt = 0; nt < 8; ++nt)
#pragma unroll
                for (int i = 0; i < 4; ++i) d1[nt][i] = g1d[nt][i];
#pragma unroll
            for (int kt = 0; kt < 3; ++kt) {
                uint32_t ah[4], al[4];
                load_afrag(ah, sb, A1BH, 112, kt * 16 + t * 2, g);
                load_afrag(al, sb, A1BL, 112, kt * 16 + t * 2, g);
                uint4 bt[8];
#pragma unroll
                for (int nt = 0; nt < 8; ++nt) bt[nt] = __ldg(&g_w1[(40 + kt * 8 + nt) * 32 + lane]);
                mma3_multi<8>(d1, ah, al, bt);
            }
            uint32_t a2h[4][4], a2l[4][4];
#pragma unroll
            for (int k2 = 0; k2 < 4; ++k2)
                pack_frag_elu(d1[2 * k2], d1[2 * k2 + 1], a2h[k2], a2l[k2]);

            // L2 (term-major per kt)
            float d2[4][4];
#pragma unroll
            for (int nt = 0; nt < 4; ++nt) dinit(d2[nt], sf, SF_BB2, nt, t);
#pragma unroll
            for (int kt = 0; kt < 4; ++kt) {
                uint4 bt[4];
#pragma unroll
                for (int nt = 0; nt < 4; ++nt)
                    bt[nt] = *reinterpret_cast<const uint4*>(sb + BW2 + ((kt * 4 + nt) * 32 + lane) * 16);
                mma3_multi<4>(d2, a2h[kt], a2l[kt], bt);
            }
            float h2[4][4];
#pragma unroll
            for (int nt = 0; nt < 4; ++nt)
#pragma unroll
                for (int i = 0; i < 4; ++i) h2[nt][i] = elu1(d2[nt][i]);
            uint32_t a3h[2][4], a3l[2][4];
#pragma unroll
            for (int k2 = 0; k2 < 2; ++k2)
                pack_frag_raw(h2[2 * k2], h2[2 * k2 + 1], a3h[k2], a3l[k2]);

            // t1 (term-major)
            float dt[4][4];
#pragma unroll
            for (int nt = 0; nt < 4; ++nt) dinit(dt[nt], sf, SF_VB1, nt, t);
#pragma unroll
            for (int kt = 0; kt < 2; ++kt) {
                uint4 bt[4];
#pragma unroll
                for (int nt = 0; nt < 4; ++nt)
                    bt[nt] = *reinterpret_cast<const uint4*>(sb + BV1 + ((kt * 4 + nt) * 32 + lane) * 16);
                mma3_multi<4>(dt, a3h[kt], a3l[kt], bt);
            }
            uint32_t t1h[2][4], t1l[2][4];
#pragma unroll
            for (int k2 = 0; k2 < 2; ++k2)
                pack_frag_elu(dt[2 * k2], dt[2 * k2 + 1], t1h[k2], t1l[k2]);

            // t2 (term-major)
            float du[4][4];
#pragma unroll
            for (int nt = 0; nt < 4; ++nt) dinit(du[nt], sf, SF_VB2, nt, t);
#pragma unroll
            for (int kt = 0; kt < 2; ++kt) {
                uint4 bt[4];
#pragma unroll
                for (int nt = 0; nt < 4; ++nt)
                    bt[nt] = *reinterpret_cast<const uint4*>(sb + BV2 + ((kt * 4 + nt) * 32 + lane) * 16);
                mma3_multi<4>(du, t1h[kt], t1l[kt], bt);
            }
            // x = h2e + elu(t2)
            float xv[4][4];
#pragma unroll
            for (int nt = 0; nt < 4; ++nt)
#pragma unroll
                for (int i = 0; i < 4; ++i) xv[nt][i] = h2[nt][i] + elu1(du[nt][i]);
            uint32_t xh[2][4], xl[2][4];
#pragma unroll
            for (int k2 = 0; k2 < 2; ++k2)
                pack_frag_raw(xv[2 * k2], xv[2 * k2 + 1], xh[k2], xl[k2]);

            // r1 += x @ rw1_v^T (term-major)
#pragma unroll
            for (int kt = 0; kt < 2; ++kt) {
                uint4 bt[4];
#pragma unroll
                for (int nt = 0; nt < 4; ++nt)
                    bt[nt] = *reinterpret_cast<const uint4*>(sb + BR1 + ((v * 8 + kt * 4 + nt) * 32 + lane) * 16);
                mma3_multi<4>(r1d, xh[kt], xl[kt], bt);
            }
        }

        // ---- head: r2 = rb2 + rw2 @ elu(r1) (term-major) ----
        uint32_t rh[2][4], rl[2][4];
#pragma unroll
        for (int k2 = 0; k2 < 2; ++k2)
            pack_frag_elu(r1d[2 * k2], r1d[2 * k2 + 1], rh[k2], rl[k2]);

        float dr[2][4];
#pragma unroll
        for (int nt = 0; nt < 2; ++nt) dinit(dr[nt], sf, SF_RB2, nt, t);
#pragma unroll
        for (int kt = 0; kt < 2; ++kt) {
            uint4 bt[2];
#pragma unroll
            for (int nt = 0; nt < 2; ++nt)
                bt[nt] = *reinterpret_cast<const uint4*>(sb + BR2 + ((kt * 2 + nt) * 32 + lane) * 16);
            mma3_multi<2>(dr, rh[kt], rl[kt], bt);
        }

        // ---- final 16->3 via one mma3 ----
        uint32_t fh[4], fl[4];
        pack_frag_elu(dr[0], dr[1], fh, fl);
        float df[4];
        dinit(df, sf, SF_RB3, 0, t);
        {
            uint4 bt = *reinterpret_cast<const uint4*>(sb + BR3 + (uint32_t)lane * 16u);
            mma3(df, fh, fl, bt);
        }
        {
            const int p0 = tile * 64 + wid * 16 + g;
            const int p1 = p0 + 8;
            if (t == 0) {
                out_rgb[(size_t)p0 * 3 + 0] = 1.f / (1.f + __expf(-df[0]));
                out_rgb[(size_t)p0 * 3 + 1] = 1.f / (1.f + __expf(-df[1]));
                out_rgb[(size_t)p1 * 3 + 0] = 1.f / (1.f + __expf(-df[2]));
                out_rgb[(size_t)p1 * 3 + 1] = 1.f / (1.f + __expf(-df[3]));
            } else if (t == 1) {
                out_rgb[(size_t)p0 * 3 + 2] = 1.f / (1.f + __expf(-df[0]));
                out_rgb[(size_t)p1 * 3 + 2] = 1.f / (1.f + __expf(-df[2]));
            }
        }
    }
}

extern "C" void kernel_launch(void* const* d_in, const int* in_sizes, int n_in,
                              void* d_out, int out_size)
{
    const float* rgb = (const float*)d_in[0];
    const float* bw1 = (const float*)d_in[1];
    const float* bb1 = (const float*)d_in[2];
    const float* bw2 = (const float*)d_in[3];
    const float* bb2 = (const float*)d_in[4];
    const float* vw1 = (const float*)d_in[5];
    const float* vb1 = (const float*)d_in[6];
    const float* vw2 = (const float*)d_in[7];
    const float* vb2 = (const float*)d_in[8];
    const float* rw1 = (const float*)d_in[9];
    const float* rb1 = (const float*)d_in[10];
    const float* rw2 = (const float*)d_in[11];
    const float* rb2 = (const float*)d_in[12];
    const float* rw3 = (const float*)d_in[13];
    const float* rb3 = (const float*)d_in[14];

    const int P = in_sizes[0] / 105;                  // 524288
    float* out_in  = (float*)d_out;                   // rgb_in : P*9
    float* out_rgb = (float*)d_out + (size_t)P * 9;   // rgb_out: P*3

    k_wpack<<<8, 256>>>(bw1);
    k_prep<<<P / 32, 256>>>(rgb, out_in, P);

    cudaFuncSetAttribute(k_tc, cudaFuncAttributeMaxDynamicSharedMemorySize, SMEM_TC);
    k_tc<<<456, 128, SMEM_TC>>>(
        bw1, bb1, bw2, bb2, vw1, vb1, vw2, vb2,
        rw1, rb1, rw2, rb2, rw3, rb3, out_rgb, P);
}

// round 16
// speedup vs baseline: 1.1652x; 1.1652x over previous
#include <cuda_runtime.h>
#include <cuda_bf16.h>
#include <cstdint>

#define P_CONST 524288

// ---- bias float indices in sf[] ----
#define SF_BB1  0
#define SF_BB2  64
#define SF_VB1  96
#define SF_VB2  128
#define SF_RB1  160
#define SF_RB2  192
#define SF_RW3  208
#define SF_RB3  256

// ---- smem byte offsets (W1A/W1B live in GLOBAL g_w1) ----
#define BW2  1152u               // 16 tiles (4x4)
#define BV1  (BW2  + 16u*512u)   // 8 tiles  (4x2)
#define BV2  (BV1  +  8u*512u)   // 8 tiles
#define BR1  (BV2  +  8u*512u)   // 24 tiles (3 views x 4x2)
#define BR2  (BR1  + 24u*512u)   // 4 tiles  (2x2)
#define AWBASE (BR2 + 4u*512u)   // per-warp A1 staging, 9216B each (4 warps)
// per warp: A1a hi[16x88 bf16]=2816, A1a lo=2816, A1b hi[16x56]=1792, A1b lo=1792
#define HSBASE (AWBASE + 4u*9216u)   // per-warp head scratch 1024B
#define SMEM_TC (HSBASE + 4u*1024u)  // 72832 B -> 3 CTAs/SM (12 warps)

__device__ float g_scr[(size_t)P_CONST * 105];   // input transposed [P/32][105][32]
__device__ uint4 g_w1[64 * 32];                  // fragment-packed W1A(40)+W1B(24) tiles

// ========================= helpers =========================
__device__ __forceinline__ float elu1(float x) {
    return x > 0.f ? x : (__expf(x) - 1.f);
}
__device__ __forceinline__ uint32_t smem_u32(const void* p) {
    uint32_t a;
    asm("{ .reg .u64 t; cvta.to.shared.u64 t, %1; cvt.u32.u64 %0, t; }" : "=r"(a) : "l"(p));
    return a;
}
__device__ __forceinline__ void bsplit(float x, __nv_bfloat16 &h, __nv_bfloat16 &l) {
    h = __float2bfloat16(x);
    l = __float2bfloat16(x - __bfloat162float(h));
}
__device__ __forceinline__ uint32_t bpack(__nv_bfloat16 a, __nv_bfloat16 b) {
    __nv_bfloat162 t(a, b);    // .x = a = low half
    return *reinterpret_cast<uint32_t*>(&t);
}
// fast pack: two fp32 (cols c,c+1) -> hi/lo bf16x2 regs
__device__ __forceinline__ void pack_hl(float x, float y, uint32_t &hi, uint32_t &lo) {
    asm("cvt.rn.bf16x2.f32 %0, %1, %2;" : "=r"(hi) : "f"(y), "f"(x));   // {y hi, x lo}
    uint32_t hxf = hi << 16;
    uint32_t hyf = hi & 0xFFFF0000u;
    float lx = x - __uint_as_float(hxf);
    float ly = y - __uint_as_float(hyf);
    asm("cvt.rn.bf16x2.f32 %0, %1, %2;" : "=r"(lo) : "f"(ly), "f"(lx));
}

// mma.m16n8k16 row.col f32 += bf16*bf16
__device__ __forceinline__ void mma_bf(float* d, const uint32_t* a, uint32_t b0, uint32_t b1) {
    asm volatile(
        "mma.sync.aligned.m16n8k16.row.col.f32.bf16.bf16.f32 "
        "{%0,%1,%2,%3}, {%4,%5,%6,%7}, {%8,%9}, {%0,%1,%2,%3};"
        : "+f"(d[0]), "+f"(d[1]), "+f"(d[2]), "+f"(d[3])
        : "r"(a[0]), "r"(a[1]), "r"(a[2]), "r"(a[3]), "r"(b0), "r"(b1));
}
// 3-term split product: D += Ah*Bh + Al*Bh + Ah*Bl
__device__ __forceinline__ void mma3(float* d, const uint32_t* ah, const uint32_t* al, uint4 bt) {
    mma_bf(d, ah, bt.x, bt.y);
    mma_bf(d, al, bt.x, bt.y);
    mma_bf(d, ah, bt.z, bt.w);
}
// ldmatrix x4: full m16k16 A fragment in one instruction
__device__ __forceinline__ void ldmA(uint32_t* a, uint32_t addr) {
    asm volatile("ldmatrix.sync.aligned.m8n8.x4.shared.b16 {%0,%1,%2,%3}, [%4];"
                 : "=r"(a[0]), "=r"(a[1]), "=r"(a[2]), "=r"(a[3]) : "r"(addr));
}
__device__ __forceinline__ void dinit(float* d, const float* sf, int boff, int nt, int t) {
    float b0 = sf[boff + nt * 8 + t * 2];
    float b1 = sf[boff + nt * 8 + t * 2 + 1];
    d[0] = b0; d[1] = b1; d[2] = b0; d[3] = b1;
}
__device__ __forceinline__ void pack_frag_elu(const float* dA, const float* dB,
                                              uint32_t* ah, uint32_t* al) {
    pack_hl(elu1(dA[0]), elu1(dA[1]), ah[0], al[0]);
    pack_hl(elu1(dA[2]), elu1(dA[3]), ah[1], al[1]);
    pack_hl(elu1(dB[0]), elu1(dB[1]), ah[2], al[2]);
    pack_hl(elu1(dB[2]), elu1(dB[3]), ah[3], al[3]);
}
__device__ __forceinline__ void pack_frag_raw(const float* dA, const float* dB,
                                              uint32_t* ah, uint32_t* al) {
    pack_hl(dA[0], dA[1], ah[0], al[0]);
    pack_hl(dA[2], dA[3], ah[1], al[1]);
    pack_hl(dB[0], dB[1], ah[2], al[2]);
    pack_hl(dB[2], dB[3], ah[3], al[3]);
}

// stage weight matrix w[N][K] (row stride ldw floats) as fragment-packed B tiles (SMEM)
__device__ void stage_B(char* sb, uint32_t off, const float* __restrict__ w,
                        int N, int K, int ldw, float scale, int NT, int KT,
                        int wid, int lane) {
    int g = lane >> 2, t = lane & 3;
    for (int tile = wid; tile < NT * KT; tile += 4) {
        int kt = tile / NT, nt = tile % NT;
        int n = nt * 8 + g;
        int k0 = kt * 16 + t * 2;
        float v0 = 0.f, v1 = 0.f, v2 = 0.f, v3 = 0.f;
        if (n < N) {
            if (k0 < K)     v0 = __ldg(w + n * ldw + k0) * scale;
            if (k0 + 1 < K) v1 = __ldg(w + n * ldw + k0 + 1) * scale;
            if (k0 + 8 < K) v2 = __ldg(w + n * ldw + k0 + 8) * scale;
            if (k0 + 9 < K) v3 = __ldg(w + n * ldw + k0 + 9) * scale;
        }
        __nv_bfloat16 h0, l0, h1, l1, h2, l2, h3, l3;
        bsplit(v0, h0, l0); bsplit(v1, h1, l1);
        bsplit(v2, h2, l2); bsplit(v3, h3, l3);
        uint4 u;
        u.x = bpack(h0, h1);
        u.y = bpack(h2, h3);
        u.z = bpack(l0, l1);
        u.w = bpack(l2, l3);
        *reinterpret_cast<uint4*>(sb + off + ((uint32_t)tile * 32u + lane) * 16u) = u;
    }
}

// ========== K0: transpose input + emit rgb_in  (+ blocks 0..7 pack W1) ===========
__global__ __launch_bounds__(256, 4)
void k_prep(const float* __restrict__ rgb, const float* __restrict__ bw1,
            float* __restrict__ out_in, int P)
{
    __shared__ float st[32 * 105];
    const int g = blockIdx.x;
    const int tid = threadIdx.x;

    // ---- W1 fragment packing (first 8 blocks only; independent of the rest) ----
    if (g < 8) {
        int gid = g * 256 + tid;              // 0..2047
        int tile = gid >> 5, lane = gid & 31;
        int gg = lane >> 2, tt = lane & 3;
        const float* w;
        int kt, nt, K;
        if (tile < 40) { kt = tile / 8; nt = tile % 8; w = bw1;      K = 70; }
        else { int u2 = tile - 40; kt = u2 / 8; nt = u2 % 8; w = bw1 + 70; K = 35; }
        int n = nt * 8 + gg;
        int k0 = kt * 16 + tt * 2;
        float v0 = 0.f, v1 = 0.f, v2 = 0.f, v3 = 0.f;
        if (k0 < K)     v0 = __ldg(w + n * 105 + k0);
        if (k0 + 1 < K) v1 = __ldg(w + n * 105 + k0 + 1);
        if (k0 + 8 < K) v2 = __ldg(w + n * 105 + k0 + 8);
        if (k0 + 9 < K) v3 = __ldg(w + n * 105 + k0 + 9);
        __nv_bfloat16 h0, l0, h1, l1, h2, l2, h3, l3;
        bsplit(v0, h0, l0); bsplit(v1, h1, l1);
        bsplit(v2, h2, l2); bsplit(v3, h3, l3);
        uint4 u;
        u.x = bpack(h0, h1);
        u.y = bpack(h2, h3);
        u.z = bpack(l0, l1);
        u.w = bpack(l2, l3);
        g_w1[tile * 32 + lane] = u;
    }

    const float4* src4 = reinterpret_cast<const float4*>(rgb + (size_t)g * 3360);
    float4* st4 = reinterpret_cast<float4*>(st);
#pragma unroll
    for (int i = tid; i < 840; i += 256) st4[i] = src4[i];
    __syncthreads();

    float* dst = g_scr + (size_t)g * 3360;
#pragma unroll
    for (int i = tid; i < 3360; i += 256) {
        int j = i >> 5, lane = i & 31;
        dst[i] = st[lane * 105 + j];
    }
    for (int i = tid; i < 288; i += 256) {
        int pl = i / 9, r = i % 9, v = r / 3, k = r % 3;
        out_in[((size_t)g * 32 + pl) * 9 + r] = st[pl * 105 + v * 35 + k];
    }
}

// ====== K1: HMMA fragment-chained MLP, 128 thr, 3 CTAs/SM (12 warps) =============
__global__ __launch_bounds__(128, 3)
void k_tc(
    const float* __restrict__ bw1, const float* __restrict__ bb1,
    const float* __restrict__ bw2, const float* __restrict__ bb2,
    const float* __restrict__ vw1, const float* __restrict__ vb1,
    const float* __restrict__ vw2, const float* __restrict__ vb2,
    const float* __restrict__ rw1, const float* __restrict__ rb1,
    const float* __restrict__ rw2, const float* __restrict__ rb2,
    const float* __restrict__ rw3, const float* __restrict__ rb3,
    float* __restrict__ out_rgb, int P)
{
    extern __shared__ char sb[];
    float* sf = reinterpret_cast<float*>(sb);
    const int tid = threadIdx.x;
    const int wid = tid >> 5;
    const int lane = tid & 31;
    const int g = lane >> 2;
    const int t = lane & 3;

    // ---- stage biases ----
    for (int i = tid; i < 64; i += 128) sf[SF_BB1 + i] = bb1[i];
    for (int i = tid; i < 32; i += 128) sf[SF_BB2 + i] = bb2[i];
    for (int i = tid; i < 32; i += 128) sf[SF_VB1 + i] = vb1[i];
    for (int i = tid; i < 32; i += 128) sf[SF_VB2 + i] = vb2[i];
    for (int i = tid; i < 32; i += 128) sf[SF_RB1 + i] = rb1[i];
    for (int i = tid; i < 16; i += 128) sf[SF_RB2 + i] = rb2[i];
    for (int i = tid; i < 48; i += 128) sf[SF_RW3 + i] = rw3[i];
    for (int i = tid; i < 8;  i += 128) sf[SF_RB3 + i] = (i < 3) ? rb3[i] : 0.f;

    // ---- stage small weights (W1 in global g_w1) ----
    stage_B(sb, BW2,  bw2,      32, 64, 64,  1.f,       4, 4, wid, lane);
    stage_B(sb, BV1,  vw1,      32, 32, 32,  1.f / 3.f, 4, 2, wid, lane);
    stage_B(sb, BV2,  vw2,      32, 32, 32,  1.f,       4, 2, wid, lane);
    for (int v = 0; v < 3; ++v)
        stage_B(sb, BR1 + (uint32_t)v * 8u * 512u, rw1 + v * 32, 32, 32, 96, 1.f, 4, 2, wid, lane);
    stage_B(sb, BR2,  rw2,      16, 32, 32,  1.f,       2, 2, wid, lane);

    // per-warp A1 staging bases
    const uint32_t aw   = AWBASE + (uint32_t)wid * 9216u;
    const uint32_t A1AH = aw, A1AL = aw + 2816u;
    const uint32_t A1BH = aw + 5632u, A1BL = aw + 7424u;
    const uint32_t HS   = HSBASE + (uint32_t)wid * 1024u;

    // ldmatrix row-base addresses (shared-space)
    const uint32_t sbase = smem_u32(sb);
    const int rsel = lane & 15;
    const int cblk = (lane >> 4) * 16;
    const uint32_t rbAH = sbase + A1AH + rsel * 176 + cblk;
    const uint32_t rbAL = rbAH + 2816u;
    const uint32_t rbBH = sbase + A1BH + rsel * 112 + cblk;
    const uint32_t rbBL = rbBH + 1792u;

    // zero pads: A1a cols 70..79, A1b cols 35..47 (written once)
    for (int i = lane; i < 160; i += 32) {
        int q = i / 10, c = 70 + i % 10;
        *reinterpret_cast<__nv_bfloat16*>(sb + A1AH + q * 176 + c * 2) = __float2bfloat16(0.f);
        *reinterpret_cast<__nv_bfloat16*>(sb + A1AL + q * 176 + c * 2) = __float2bfloat16(0.f);
    }
    for (int i = lane; i < 208; i += 32) {
        int q = i / 13, c = 35 + i % 13;
        *reinterpret_cast<__nv_bfloat16*>(sb + A1BH + q * 112 + c * 2) = __float2bfloat16(0.f);
        *reinterpret_cast<__nv_bfloat16*>(sb + A1BL + q * 112 + c * 2) = __float2bfloat16(0.f);
    }
    __syncthreads();   // staging complete; warps independent from here

    const int ntile = P / 64;
    for (int tile = blockIdx.x; tile < ntile; tile += gridDim.x) {
        const float* gb = g_scr + (size_t)(tile * 2 + (wid >> 1)) * 3360 + (wid & 1) * 16;

        // ---- stats -> A1a (cols 0..34 mean, 35..69 var) ----
        for (int i = lane; i < 560; i += 32) {
            int q = i & 15, k = i >> 4;
            float a = __ldg(gb + k * 32 + q);
            float b = __ldg(gb + (35 + k) * 32 + q);
            float c = __ldg(gb + (70 + k) * 32 + q);
            float m = (a + b + c) * (1.f / 3.f);
            float qv = fmaf(-m, m, fmaf(a, a, fmaf(b, b, c * c)) * (1.f / 3.f));
            __nv_bfloat16 h, l;
            bsplit(m, h, l);
            *reinterpret_cast<__nv_bfloat16*>(sb + A1AH + q * 176 + k * 2) = h;
            *reinterpret_cast<__nv_bfloat16*>(sb + A1AL + q * 176 + k * 2) = l;
            bsplit(qv, h, l);
            *reinterpret_cast<__nv_bfloat16*>(sb + A1AH + q * 176 + (35 + k) * 2) = h;
            *reinterpret_cast<__nv_bfloat16*>(sb + A1AL + q * 176 + (35 + k) * 2) = l;
        }
        __syncwarp();

        // ---- g1 = bb1 + A1a @ W1a^T (ldmatrix A, global W1 tiles prefetched) ----
        float g1d[8][4];
#pragma unroll
        for (int nt = 0; nt < 8; ++nt) dinit(g1d[nt], sf, SF_BB1, nt, t);
#pragma unroll
        for (int kt = 0; kt < 5; ++kt) {
            uint32_t ah[4], al[4];
            ldmA(ah, rbAH + kt * 32);
            ldmA(al, rbAL + kt * 32);
            uint4 bt[8];
#pragma unroll
            for (int nt = 0; nt < 8; ++nt) bt[nt] = __ldg(&g_w1[(kt * 8 + nt) * 32 + lane]);
#pragma unroll
            for (int nt = 0; nt < 8; ++nt) mma3(g1d[nt], ah, al, bt[nt]);
        }

        float r1d[4][4];
#pragma unroll
        for (int nt = 0; nt < 4; ++nt) dinit(r1d[nt], sf, SF_RB1, nt, t);

        // ---- per-view ----
#pragma unroll 1
        for (int v = 0; v < 3; ++v) {
            // A1b = f_v (cols 0..34)
            for (int i = lane; i < 560; i += 32) {
                int q = i & 15, k = i >> 4;
                float fv = __ldg(gb + (v * 35 + k) * 32 + q);
                __nv_bfloat16 h, l;
                bsplit(fv, h, l);
                *reinterpret_cast<__nv_bfloat16*>(sb + A1BH + q * 112 + k * 2) = h;
                *reinterpret_cast<__nv_bfloat16*>(sb + A1BL + q * 112 + k * 2) = l;
            }
            __syncwarp();

            // L1: d1 = g1 + A1b @ W1b^T
            float d1[8][4];
#pragma unroll
            for (int nt = 0; nt < 8; ++nt)
#pragma unroll
                for (int i = 0; i < 4; ++i) d1[nt][i] = g1d[nt][i];
#pragma unroll
            for (int kt = 0; kt < 3; ++kt) {
                uint32_t ah[4], al[4];
                ldmA(ah, rbBH + kt * 32);
                ldmA(al, rbBL + kt * 32);
                uint4 bt[8];
#pragma unroll
                for (int nt = 0; nt < 8; ++nt) bt[nt] = __ldg(&g_w1[(40 + kt * 8 + nt) * 32 + lane]);
#pragma unroll
                for (int nt = 0; nt < 8; ++nt) mma3(d1[nt], ah, al, bt[nt]);
            }
            // chain: A2 = elu(d1)
            uint32_t a2h[4][4], a2l[4][4];
#pragma unroll
            for (int k2 = 0; k2 < 4; ++k2)
                pack_frag_elu(d1[2 * k2], d1[2 * k2 + 1], a2h[k2], a2l[k2]);

            // L2
            float d2[4][4];
#pragma unroll
            for (int nt = 0; nt < 4; ++nt) dinit(d2[nt], sf, SF_BB2, nt, t);
#pragma unroll
            for (int kt = 0; kt < 4; ++kt)
#pragma unroll
                for (int nt = 0; nt < 4; ++nt) {
                    uint4 bt = *reinterpret_cast<const uint4*>(sb + BW2 + ((kt * 4 + nt) * 32 + lane) * 16);
                    mma3(d2[nt], a2h[kt], a2l[kt], bt);
                }
            float h2[4][4];
#pragma unroll
            for (int nt = 0; nt < 4; ++nt)
#pragma unroll
                for (int i = 0; i < 4; ++i) h2[nt][i] = elu1(d2[nt][i]);
            uint32_t a3h[2][4], a3l[2][4];
#pragma unroll
            for (int k2 = 0; k2 < 2; ++k2)
                pack_frag_raw(h2[2 * k2], h2[2 * k2 + 1], a3h[k2], a3l[k2]);

            // t1
            float dt[4][4];
#pragma unroll
            for (int nt = 0; nt < 4; ++nt) dinit(dt[nt], sf, SF_VB1, nt, t);
#pragma unroll
            for (int kt = 0; kt < 2; ++kt)
#pragma unroll
                for (int nt = 0; nt < 4; ++nt) {
                    uint4 bt = *reinterpret_cast<const uint4*>(sb + BV1 + ((kt * 4 + nt) * 32 + lane) * 16);
                    mma3(dt[nt], a3h[kt], a3l[kt], bt);
                }
            uint32_t t1h[2][4], t1l[2][4];
#pragma unroll
            for (int k2 = 0; k2 < 2; ++k2)
                pack_frag_elu(dt[2 * k2], dt[2 * k2 + 1], t1h[k2], t1l[k2]);

            // t2
            float du[4][4];
#pragma unroll
            for (int nt = 0; nt < 4; ++nt) dinit(du[nt], sf, SF_VB2, nt, t);
#pragma unroll
            for (int kt = 0; kt < 2; ++kt)
#pragma unroll
                for (int nt = 0; nt < 4; ++nt) {
                    uint4 bt = *reinterpret_cast<const uint4*>(sb + BV2 + ((kt * 4 + nt) * 32 + lane) * 16);
                    mma3(du[nt], t1h[kt], t1l[kt], bt);
                }
            // x = h2e + elu(t2)
            float xv[4][4];
#pragma unroll
            for (int nt = 0; nt < 4; ++nt)
#pragma unroll
                for (int i = 0; i < 4; ++i) xv[nt][i] = h2[nt][i] + elu1(du[nt][i]);
            uint32_t xh[2][4], xl[2][4];
#pragma unroll
            for (int k2 = 0; k2 < 2; ++k2)
                pack_frag_raw(xv[2 * k2], xv[2 * k2 + 1], xh[k2], xl[k2]);

            // r1 += x @ rw1_v^T
#pragma unroll
            for (int kt = 0; kt < 2; ++kt)
#pragma unroll
                for (int nt = 0; nt < 4; ++nt) {
                    uint4 bt = *reinterpret_cast<const uint4*>(sb + BR1 + ((v * 8 + kt * 4 + nt) * 32 + lane) * 16);
                    mma3(r1d[nt], xh[kt], xl[kt], bt);
                }
        }

        // ---- head ----
        uint32_t rh[2][4], rl[2][4];
#pragma unroll
        for (int k2 = 0; k2 < 2; ++k2)
            pack_frag_elu(r1d[2 * k2], r1d[2 * k2 + 1], rh[k2], rl[k2]);

        float dr[2][4];
#pragma unroll
        for (int nt = 0; nt < 2; ++nt) dinit(dr[nt], sf, SF_RB2, nt, t);
#pragma unroll
        for (int kt = 0; kt < 2; ++kt)
#pragma unroll
            for (int nt = 0; nt < 2; ++nt) {
                uint4 bt = *reinterpret_cast<const uint4*>(sb + BR2 + ((kt * 2 + nt) * 32 + lane) * 16);
                mma3(dr[nt], rh[kt], rl[kt], bt);
            }

        // r2e -> fp32 head scratch [16 pts][16]
#pragma unroll
        for (int nt = 0; nt < 2; ++nt) {
            int bc = nt * 8 + t * 2;
            *reinterpret_cast<float*>(sb + HS + (g * 16 + bc) * 4)           = elu1(dr[nt][0]);
            *reinterpret_cast<float*>(sb + HS + (g * 16 + bc + 1) * 4)       = elu1(dr[nt][1]);
            *reinterpret_cast<float*>(sb + HS + ((g + 8) * 16 + bc) * 4)     = elu1(dr[nt][2]);
            *reinterpret_cast<float*>(sb + HS + ((g + 8) * 16 + bc + 1) * 4) = elu1(dr[nt][3]);
        }
        __syncwarp();
        if (lane < 16) {
            const float* rr = reinterpret_cast<const float*>(sb + HS + lane * 64);
            const int p = tile * 64 + wid * 16 + lane;
#pragma unroll
            for (int c = 0; c < 3; ++c) {
                float a = sf[SF_RB3 + c];
#pragma unroll
                for (int k = 0; k < 16; ++k)
                    a = fmaf(rr[k], sf[SF_RW3 + c * 16 + k], a);
                out_rgb[(size_t)p * 3 + c] = 1.f / (1.f + __expf(-a));
            }
        }
        __syncwarp();
    }
}

extern "C" void kernel_launch(void* const* d_in, const int* in_sizes, int n_in,
                              void* d_out, int out_size)
{
    const float* rgb = (const float*)d_in[0];
    const float* bw1 = (const float*)d_in[1];
    const float* bb1 = (const float*)d_in[2];
    const float* bw2 = (const float*)d_in[3];
    const float* bb2 = (const float*)d_in[4];
    const float* vw1 = (const float*)d_in[5];
    const float* vb1 = (const float*)d_in[6];
    const float* vw2 = (const float*)d_in[7];
    const float* vb2 = (const float*)d_in[8];
    const float* rw1 = (const float*)d_in[9];
    const float* rb1 = (const float*)d_in[10];
    const float* rw2 = (const float*)d_in[11];
    const float* rb2 = (const float*)d_in[12];
    const float* rw3 = (const float*)d_in[13];
    const float* rb3 = (const float*)d_in[14];

    const int P = in_sizes[0] / 105;                  // 524288
    float* out_in  = (float*)d_out;                   // rgb_in : P*9
    float* out_rgb = (float*)d_out + (size_t)P * 9;   // rgb_out: P*3

    // K0: input transpose + rgb_in (+ W1 fragment packing in blocks 0..7)
    k_prep<<<P / 32, 256>>>(rgb, bw1, out_in, P);

    // K1: HMMA fragment-chained MLP (persistent, 3 CTAs/SM = 12 warps)
    cudaFuncSetAttribute(k_tc, cudaFuncAttributeMaxDynamicSharedMemorySize, SMEM_TC);
    k_tc<<<456, 128, SMEM_TC>>>(
        bw1, bb1, bw2, bb2, vw1, vb1, vw2, vb2,
        rw1, rb1, rw2, rb2, rw3, rb3, out_rgb, P);
}